// round 12
// baseline (speedup 1.0000x reference)
#include <cuda_runtime.h>
#include <cuda_bf16.h>
#include <cuda_pipeline.h>
#include <math.h>

// Problem constants
#define PB 32
#define PN 4096
#define PD 768
#define PC 10
#define PK 16
#define NCHUNK 8           // chunks per batch
#define CH 512             // rows per chunk

// Scratch
__device__ unsigned g_scores_u[PB * PN];                 // pre-flipped scores
__device__ unsigned g_cand_v[PB * NCHUNK * PK];          // per-chunk top-16 values
__device__ unsigned g_cand_i[PB * NCHUNK * PK];          // per-chunk top-16 row idx

// Monotone 32-bit mapping: flip(a) > flip(b)  <=>  a > b (as floats)
__device__ __forceinline__ unsigned flip_f32(float s) {
    unsigned u = __float_as_uint(s);
    return (u & 0x80000000u) ? ~u : (u | 0x80000000u);
}

// ---------------------------------------------------------------------------
// Kernel 1: scores. One warp per row. 7.0 TB/s measured — frozen.
// Also zeroes the A output region.
// ---------------------------------------------------------------------------
__global__ void __launch_bounds__(256) score_kernel(
    const float* __restrict__ H,
    const float* __restrict__ w_score,
    const float* __restrict__ b_score,
    float* __restrict__ A_out)
{
    const int tid_global = blockIdx.x * blockDim.x + threadIdx.x;
    const int warp = tid_global >> 5;
    const int lane = threadIdx.x & 31;

    if (tid_global < PB * PN) A_out[tid_global] = 0.0f;
    if (warp >= PB * PN) return;

    const float4* __restrict__ h4 = (const float4*)(H + (size_t)warp * PD);
    const float4* __restrict__ w4 = (const float4*)w_score;

    float sum = 0.0f;
    #pragma unroll
    for (int k = 0; k < PD / 128; k++) {
        float4 a = __ldcs(&h4[lane + k * 32]);
        float4 b = __ldg(&w4[lane + k * 32]);
        sum += a.x * b.x + a.y * b.y + a.z * b.z + a.w * b.w;
    }
    #pragma unroll
    for (int o = 16; o > 0; o >>= 1)
        sum += __shfl_down_sync(0xFFFFFFFFu, sum, o);

    if (lane == 0) g_scores_u[warp] = flip_f32(sum + b_score[0]);
}

// ---------------------------------------------------------------------------
// Kernel 1.5: per-chunk exact top-16. 256 CTAs (8 per batch), 256 threads.
// Each CTA: 512 scores -> 16 candidates. Tie-break: lowest row idx.
// ---------------------------------------------------------------------------
__global__ void __launch_bounds__(256) chunk_topk_kernel()
{
    const int c     = blockIdx.x;           // 0..255
    const int b     = c >> 3;
    const int chunk = c & 7;
    const int tid   = threadIdx.x;
    const int warp  = tid >> 5;
    const int lane  = tid & 31;
    const unsigned FULL = 0xFFFFFFFFu;
    const unsigned BIGI = 0xFFFFFFFFu;

    __shared__ unsigned cv[8 * PK];
    __shared__ unsigned ci[8 * PK];

    const unsigned* __restrict__ sb = g_scores_u + b * PN + chunk * CH;

    // each warp: top-16 of its 64 scores (2 regs/lane)
    unsigned v0 = sb[warp * 64 + lane];
    unsigned v1 = sb[warp * 64 + 32 + lane];
    unsigned i0 = (unsigned)(chunk * CH + warp * 64 + lane);
    unsigned i1 = i0 + 32;

    #pragma unroll
    for (int it = 0; it < PK; it++) {
        bool sel0 = (v0 > v1) || (v0 == v1 && i0 < i1);
        unsigned bv = sel0 ? v0 : v1;
        unsigned bi = sel0 ? i0 : i1;
        unsigned mx = __reduce_max_sync(FULL, bv);
        unsigned my = (bv == mx) ? bi : BIGI;
        unsigned wi = __reduce_min_sync(FULL, my);
        if (v0 == mx && i0 == wi) { v0 = 0u; i0 = BIGI; }
        if (v1 == mx && i1 == wi) { v1 = 0u; i1 = BIGI; }
        if (lane == 0) { cv[warp * PK + it] = mx; ci[warp * PK + it] = wi; }
    }
    __syncthreads();

    // warp 0: merge 128 -> chunk top-16
    if (warp == 0) {
        unsigned vv[4], vi[4];
        #pragma unroll
        for (int j = 0; j < 4; j++) {
            vv[j] = cv[j * 32 + lane];
            vi[j] = ci[j * 32 + lane];
        }
        #pragma unroll
        for (int it = 0; it < PK; it++) {
            unsigned bv = vv[0], bi = vi[0];
            #pragma unroll
            for (int j = 1; j < 4; j++) {
                bool better = (vv[j] > bv) || (vv[j] == bv && vi[j] < bi);
                if (better) { bv = vv[j]; bi = vi[j]; }
            }
            unsigned mx = __reduce_max_sync(FULL, bv);
            unsigned my = (bv == mx) ? bi : BIGI;
            unsigned wi = __reduce_min_sync(FULL, my);
            #pragma unroll
            for (int j = 0; j < 4; j++)
                if (vv[j] == mx && vi[j] == wi) { vv[j] = 0u; vi[j] = BIGI; }
            if (lane == 0) { g_cand_v[c * PK + it] = mx; g_cand_i[c * PK + it] = wi; }
        }
    }
}

// ---------------------------------------------------------------------------
// Kernel 2: merge 128 candidates -> top-16; scatter A; gather+mean; GEMV.
// 32 CTAs (1 per batch), 256 threads.
// ---------------------------------------------------------------------------
__global__ void __launch_bounds__(256) epilogue_kernel(
    const float* __restrict__ H,
    const float* __restrict__ W_cls,   // [D, C] row-major
    const float* __restrict__ b_cls,   // [C]
    float* __restrict__ logits_out,    // d_out, size PB*PC
    float* __restrict__ A_out)         // d_out + PB*PC, size PB*PN
{
    const int b    = blockIdx.x;
    const int tid  = threadIdx.x;
    const int warp = tid >> 5;
    const int lane = tid & 31;
    const unsigned FULL = 0xFFFFFFFFu;
    const unsigned BIGI = 0xFFFFFFFFu;

    __shared__ __align__(16) float sW[PD * PC];  // 30720 B
    __shared__ float partial[8][PC];

    // ---- 0. W_cls -> smem prefetch (hidden behind merge) ----
    {
        const float4* __restrict__ Wg = (const float4*)W_cls;
        float4* Ws = (float4*)sW;
        #pragma unroll
        for (int i = 0; i < 8; i++) {
            int idx = tid + i * 256;
            if (idx < (PD * PC) / 4)
                __pipeline_memcpy_async(&Ws[idx], &Wg[idx], 16);
        }
        __pipeline_commit();
    }

    // ---- 1. All warps redundantly merge 128 candidates -> top-16 ----
    int t[PK]; unsigned myTop = 0;
    {
        unsigned vv[4], vi[4];
        const unsigned* __restrict__ gv = g_cand_v + b * (NCHUNK * PK);
        const unsigned* __restrict__ gi = g_cand_i + b * (NCHUNK * PK);
        #pragma unroll
        for (int j = 0; j < 4; j++) {
            vv[j] = __ldg(&gv[j * 32 + lane]);
            vi[j] = __ldg(&gi[j * 32 + lane]);
        }
        #pragma unroll
        for (int it = 0; it < PK; it++) {
            unsigned bv = vv[0], bi = vi[0];
            #pragma unroll
            for (int j = 1; j < 4; j++) {
                bool better = (vv[j] > bv) || (vv[j] == bv && vi[j] < bi);
                if (better) { bv = vv[j]; bi = vi[j]; }
            }
            unsigned mx = __reduce_max_sync(FULL, bv);
            unsigned my = (bv == mx) ? bi : BIGI;
            unsigned wi = __reduce_min_sync(FULL, my);
            #pragma unroll
            for (int j = 0; j < 4; j++)
                if (vv[j] == mx && vi[j] == wi) { vv[j] = 0u; vi[j] = BIGI; }
            t[it] = (int)wi;
            if (lane == it) myTop = wi;
        }
    }

    // ---- 2. Scatter attention mask A ----
    if (warp == 0 && lane < PK) A_out[b * PN + (int)myTop] = 1.0f / (float)PK;

    // ---- 3. Gather + mean (all warps, 24 lanes x float4) + partial GEMV ----
    const float4* __restrict__ H4 = (const float4*)H;
    float4 m = make_float4(0.f, 0.f, 0.f, 0.f);
    const int d4 = warp * 24 + ((lane < 24) ? lane : 23);
    if (lane < 24) {
        #pragma unroll
        for (int j = 0; j < PK; j++) {
            float4 h = __ldcs(&H4[((size_t)b * PN + t[j]) * (PD / 4) + d4]);
            m.x += h.x; m.y += h.y; m.z += h.z; m.w += h.w;
        }
        const float inv = 1.0f / (float)PK;
        m.x *= inv; m.y *= inv; m.z *= inv; m.w *= inv;
    }
    __pipeline_wait_prior(0);

    float p[PC];
    #pragma unroll
    for (int c = 0; c < PC; c++) {
        const float* w0 = sW + (d4 * 4) * PC + c;
        p[c] = m.x * w0[0] + m.y * w0[PC] + m.z * w0[2 * PC] + m.w * w0[3 * PC];
    }
    #pragma unroll
    for (int c = 0; c < PC; c++) {
        #pragma unroll
        for (int o = 16; o > 0; o >>= 1)
            p[c] += __shfl_xor_sync(FULL, p[c], o);
    }
    if (lane == 0) {
        #pragma unroll
        for (int c = 0; c < PC; c++) partial[warp][c] = p[c];
    }
    __syncthreads();

    // ---- 4. Final logits ----
    if (tid < PC) {
        float acc = b_cls[tid];
        #pragma unroll
        for (int w = 0; w < 8; w++) acc += partial[w][tid];
        logits_out[b * PC + tid] = acc;
    }
}

// ---------------------------------------------------------------------------
// Launch
// Inputs (metadata order): H [B,N,D] f32, w_score [D] f32, b_score [] f32,
//                          W_cls [D,C] f32, b_cls [C] f32.
// Output: logits [B,C] (320 floats) followed by A [B,N,1] (131072 floats).
// ---------------------------------------------------------------------------
extern "C" void kernel_launch(void* const* d_in, const int* in_sizes, int n_in,
                              void* d_out, int out_size)
{
    const float* H       = (const float*)d_in[0];
    const float* w_score = (const float*)d_in[1];
    const float* b_score = (const float*)d_in[2];
    const float* W_cls   = (const float*)d_in[3];
    const float* b_cls   = (const float*)d_in[4];

    float* logits_out = (float*)d_out;
    float* A_out      = (float*)d_out + PB * PC;

    const int rows = PB * PN;
    const int blocks1 = (rows + 7) / 8;
    score_kernel<<<blocks1, 256>>>(H, w_score, b_score, A_out);

    chunk_topk_kernel<<<PB * NCHUNK, 256>>>();

    epilogue_kernel<<<PB, 256>>>(H, W_cls, b_cls, logits_out, A_out);
}